// round 12
// baseline (speedup 1.0000x reference)
#include <cuda_runtime.h>
#include <cuda_bf16.h>

// scatter_mean via PRE-DIVIDED two-phase scatter:
//   out[m,c] = sum_{i: idx[i]==m} in[i,c] / count_m   (== mean; empty -> 0)
// N = 4,000,000 rows, C = 16 fp32, M = 500,000 segments, idx int32.
//
// Binder (R3/R7/R8 evidence): L2 atomic-ALU wavefront rate ~3.85us/M-wf.
// Phase 1 scatters counts (4M wf). Phase 2 loads final count[s] (L2-hit,
// data path) and REDs v*(1/c) straight into d_out (16M wf). No finalize:
// the 64MB RMW pass is gone. Empty segments stay at memset-zero, matching
// the reference's max(count,1) clamp.

#define CHANNELS 16
#define MAX_SEGMENTS 500000

__device__ float g_counts[MAX_SEGMENTS];

// ---------------------------------------------------------------------------
// Phase 1: count scatter. One thread per row: one scalar RED per row.
// ---------------------------------------------------------------------------
__global__ void __launch_bounds__(256, 8)
dve_count_kernel(const int* __restrict__ idx, int n) {
    int row = blockIdx.x * blockDim.x + threadIdx.x;
    if (row >= n) return;
    atomicAdd(&g_counts[__ldg(idx + row)], 1.0f);
}

// ---------------------------------------------------------------------------
// Phase 2: data scatter with pre-divide. Quad-per-row: each lane loads one
// float4, the quad shares count[s] (one L2-hit wavefront), scales by 1/c,
// and REDs 16B into the quad's slot of the 64B destination row.
// ---------------------------------------------------------------------------
__global__ void __launch_bounds__(256, 8)
dve_scatter_div_kernel(const float4* __restrict__ in,
                       const int* __restrict__ idx,
                       float4* __restrict__ sums4,
                       int n) {
    int t = blockIdx.x * blockDim.x + threadIdx.x;   // [0, 4n)
    int row = t >> 2;
    int q = t & 3;
    if (row >= n) return;

    int s = __ldg(idx + row);                         // quad shares a sector
    float c = __ldg(&g_counts[s]);                    // final count, >=1 here
    float4 v = __ldg(in + (size_t)row * 4 + q);       // warp reads 8 rows=512B
    float inv = 1.0f / fmaxf(c, 1.0f);

    v.x *= inv; v.y *= inv; v.z *= inv; v.w *= inv;

    float4* p = sums4 + (size_t)s * 4 + q;            // quad covers 64B row
    asm volatile("red.global.add.v4.f32 [%0], {%1, %2, %3, %4};"
                 :: "l"(p), "f"(v.x), "f"(v.y), "f"(v.z), "f"(v.w) : "memory");
}

// ---------------------------------------------------------------------------
// Launch
// ---------------------------------------------------------------------------
extern "C" void kernel_launch(void* const* d_in, const int* in_sizes, int n_in,
                              void* d_out, int out_size) {
    const float4* in = (const float4*)d_in[0];   // [N, 16] fp32
    const int* idx = (const int*)d_in[1];        // [N] int32
    float* out = (float*)d_out;                  // [M, 16] fp32

    int n = in_sizes[0] / CHANNELS;   // 4,000,000
    int m = out_size / CHANNELS;      // 500,000

    // Zero output + counts via HW memset nodes (graph-capturable, no alloc).
    void* counts_ptr = nullptr;
    cudaGetSymbolAddress(&counts_ptr, g_counts);
    cudaMemsetAsync(d_out, 0, (size_t)out_size * sizeof(float), 0);
    cudaMemsetAsync(counts_ptr, 0, (size_t)m * sizeof(float), 0);

    {
        int threads = 256;
        int blocks = (n + threads - 1) / threads;         // 15625
        dve_count_kernel<<<blocks, threads>>>(idx, n);
    }
    {
        int threads = 256;
        long long total = (long long)n * 4;
        int blocks = (int)((total + threads - 1) / threads);  // 62500
        dve_scatter_div_kernel<<<blocks, threads>>>(in, idx, (float4*)out, n);
    }
}

// round 13
// speedup vs baseline: 1.0122x; 1.0122x over previous
#include <cuda_runtime.h>
#include <cuda_bf16.h>

// scatter_mean: out[m, c] = sum_{i: idx[i]==m} in[i, c] / max(count_m, 1)
// N = 4,000,000 rows, C = 16 fp32, M = 500,000 segments, idx int32.
//
// Final structure (R6-R12 evidence):
//   - Combined quad-REDG scatter is L1tex-wavefront bound at ~77us; the
//     count REDs ride free inside that budget (R12: data-only was also 77).
//   - Pre-divide/two-phase loses: separate count pass is lane-bound ~19us.
//   - Finalize best form: grid-strided MLP=2, fully coalesced (~11.3us).
//   - g_counts re-zeroed by finalize -> no counts memset node. __device__
//     globals start zeroed; every call restores the invariant.

#define CHANNELS 16
#define MAX_SEGMENTS 500000

__device__ float g_counts[MAX_SEGMENTS];

// ---------------------------------------------------------------------------
// Scatter-add, 4 lanes per row (quad-per-row). Each lane: 1 float4 load +
// 1 red.global.add.v4.f32 (16B); quad covers one 64B destination row.
// Lane 0 of each quad adds the count.
// ---------------------------------------------------------------------------
__global__ void __launch_bounds__(256, 8)
dve_scatter_kernel(const float4* __restrict__ in,
                   const int* __restrict__ idx,
                   float4* __restrict__ sums4,
                   int n) {
    int t = blockIdx.x * blockDim.x + threadIdx.x;   // [0, 4n)
    int row = t >> 2;
    int q = t & 3;
    if (row >= n) return;

    int s = __ldg(idx + row);                         // quad lanes share a sector
    float4 v = __ldg(in + (size_t)row * 4 + q);       // warp reads 8 rows = 512B

    float4* p = sums4 + (size_t)s * 4 + q;            // quad covers one 64B row
    asm volatile("red.global.add.v4.f32 [%0], {%1, %2, %3, %4};"
                 :: "l"(p), "f"(v.x), "f"(v.y), "f"(v.z), "f"(v.w) : "memory");

    if (q == 0)
        atomicAdd(&g_counts[s], 1.0f);
}

// ---------------------------------------------------------------------------
// Finalize: 2 grid-strided float4s per thread (R9 form, best measured).
// All loads issued before dependent math; every access fully coalesced.
// After using a segment's count, quad-lane 0 re-zeroes it (replaces the
// counts memset node). A segment's 4 covering threads are consecutive
// lanes of one warp, and the count load instruction precedes the store,
// so the re-zero cannot race the loads.
// ---------------------------------------------------------------------------
__global__ void __launch_bounds__(256, 8)
dve_finalize_kernel(float4* __restrict__ out, int total4) {
    int stride = gridDim.x * blockDim.x;
    int t0 = blockIdx.x * blockDim.x + threadIdx.x;
    int t1 = t0 + stride;

    if (t1 < total4) {
        float c0 = g_counts[t0 >> 2];
        float c1 = g_counts[t1 >> 2];
        float4 v0 = out[t0];
        float4 v1 = out[t1];
        if ((t0 & 3) == 0) g_counts[t0 >> 2] = 0.0f;
        if ((t1 & 3) == 0) g_counts[t1 >> 2] = 0.0f;
        float i0 = 1.0f / fmaxf(c0, 1.0f);
        float i1 = 1.0f / fmaxf(c1, 1.0f);
        v0.x *= i0; v0.y *= i0; v0.z *= i0; v0.w *= i0;
        v1.x *= i1; v1.y *= i1; v1.z *= i1; v1.w *= i1;
        out[t0] = v0;
        out[t1] = v1;
    } else if (t0 < total4) {
        float c = g_counts[t0 >> 2];
        float4 v = out[t0];
        if ((t0 & 3) == 0) g_counts[t0 >> 2] = 0.0f;
        float inv = 1.0f / fmaxf(c, 1.0f);
        v.x *= inv; v.y *= inv; v.z *= inv; v.w *= inv;
        out[t0] = v;
    }
}

// ---------------------------------------------------------------------------
// Launch
// ---------------------------------------------------------------------------
extern "C" void kernel_launch(void* const* d_in, const int* in_sizes, int n_in,
                              void* d_out, int out_size) {
    const float4* in = (const float4*)d_in[0];   // [N, 16] fp32
    const int* idx = (const int*)d_in[1];        // [N] int32
    float* out = (float*)d_out;                  // [M, 16] fp32

    int n = in_sizes[0] / CHANNELS;   // 4,000,000
    int m = out_size / CHANNELS;      // 500,000
    (void)m;

    // Zero output sums via HW memset node. Counts are zero by invariant
    // (module-load init + finalize re-zero each call).
    cudaMemsetAsync(d_out, 0, (size_t)out_size * sizeof(float), 0);

    {
        int threads = 256;
        long long total = (long long)n * 4;
        int blocks = (int)((total + threads - 1) / threads);
        dve_scatter_kernel<<<blocks, threads>>>(in, idx, (float4*)out, n);
    }
    {
        int threads = 256;
        int total4 = out_size / 4;                // 2,000,000 float4s
        int per_block = threads * 2;
        int blocks = (total4 + per_block - 1) / per_block;  // 3907
        dve_finalize_kernel<<<blocks, threads>>>((float4*)out, total4);
    }
}

// round 16
// speedup vs baseline: 1.0622x; 1.0494x over previous
#include <cuda_runtime.h>
#include <cuda_bf16.h>

// scatter_mean: out[m, c] = sum_{i: idx[i]==m} in[i, c] / max(count_m, 1)
// N = 4,000,000 rows, C = 16 channels fp32, M = 500,000 segments, idx int32.
//
// Final form (R11 configuration; measured optimum across 13 rounds):
//   HW memsets (~5us) -> combined quad-REDG scatter (per-SM L1tex reduction-
//   wavefront floor, ~77us; count REDs ride free in the same budget) ->
//   grid-strided MLP=3 finalize (~11.6us plateau).
// Falsified alternatives: TMA bulk-reduce hybrid (shares command path),
// two-phase pre-divide (count pass lane-bound), consecutive-per-thread
// finalize (breaks coalescing), fused counts re-zero (store-alias
// serialization, +15us).

#define CHANNELS 16
#define MAX_SEGMENTS 500000

__device__ float g_counts[MAX_SEGMENTS];

// ---------------------------------------------------------------------------
// Scatter-add, 4 lanes per row (quad-per-row). Each lane: 1 float4 load +
// 1 red.global.add.v4.f32 (16B); quad covers one 64B destination row.
// Lane 0 of each quad adds the count.
// ---------------------------------------------------------------------------
__global__ void __launch_bounds__(256, 8)
dve_scatter_kernel(const float4* __restrict__ in,
                   const int* __restrict__ idx,
                   float4* __restrict__ sums4,
                   int n) {
    int t = blockIdx.x * blockDim.x + threadIdx.x;   // [0, 4n)
    int row = t >> 2;
    int q = t & 3;
    if (row >= n) return;

    int s = __ldg(idx + row);                         // quad lanes share a sector
    float4 v = __ldg(in + (size_t)row * 4 + q);       // warp reads 8 rows = 512B

    float4* p = sums4 + (size_t)s * 4 + q;            // quad covers one 64B row
    asm volatile("red.global.add.v4.f32 [%0], {%1, %2, %3, %4};"
                 :: "l"(p), "f"(v.x), "f"(v.y), "f"(v.z), "f"(v.w) : "memory");

    if (q == 0)
        atomicAdd(&g_counts[s], 1.0f);
}

// ---------------------------------------------------------------------------
// Finalize: 3 grid-strided float4s per thread, all loads (3 data + 3 count)
// issued before any dependent math. Every LDG/STG is warp-contiguous.
// ~667K threads keeps 18x oversubscription for occupancy-side hiding.
// ---------------------------------------------------------------------------
__global__ void __launch_bounds__(256, 8)
dve_finalize_kernel(float4* __restrict__ out, int total4) {
    int stride = gridDim.x * blockDim.x;
    int t0 = blockIdx.x * blockDim.x + threadIdx.x;
    int t1 = t0 + stride;
    int t2 = t1 + stride;

    if (t2 < total4) {
        float c0 = g_counts[t0 >> 2];
        float c1 = g_counts[t1 >> 2];
        float c2 = g_counts[t2 >> 2];
        float4 v0 = out[t0];
        float4 v1 = out[t1];
        float4 v2 = out[t2];
        float i0 = 1.0f / fmaxf(c0, 1.0f);
        float i1 = 1.0f / fmaxf(c1, 1.0f);
        float i2 = 1.0f / fmaxf(c2, 1.0f);
        v0.x *= i0; v0.y *= i0; v0.z *= i0; v0.w *= i0;
        v1.x *= i1; v1.y *= i1; v1.z *= i1; v1.w *= i1;
        v2.x *= i2; v2.y *= i2; v2.z *= i2; v2.w *= i2;
        out[t0] = v0;
        out[t1] = v1;
        out[t2] = v2;
    } else {
        for (int t = t0; t < total4; t += stride) {
            float inv = 1.0f / fmaxf(g_counts[t >> 2], 1.0f);
            float4 v = out[t];
            v.x *= inv; v.y *= inv; v.z *= inv; v.w *= inv;
            out[t] = v;
        }
    }
}

// ---------------------------------------------------------------------------
// Launch
// ---------------------------------------------------------------------------
extern "C" void kernel_launch(void* const* d_in, const int* in_sizes, int n_in,
                              void* d_out, int out_size) {
    const float4* in = (const float4*)d_in[0];   // [N, 16] fp32
    const int* idx = (const int*)d_in[1];        // [N] int32
    float* out = (float*)d_out;                  // [M, 16] fp32

    int n = in_sizes[0] / CHANNELS;   // 4,000,000
    int m = out_size / CHANNELS;      // 500,000

    // Zero sums + counts via HW memset nodes (graph-capturable, no alloc).
    void* counts_ptr = nullptr;
    cudaGetSymbolAddress(&counts_ptr, g_counts);
    cudaMemsetAsync(d_out, 0, (size_t)out_size * sizeof(float), 0);
    cudaMemsetAsync(counts_ptr, 0, (size_t)m * sizeof(float), 0);

    {
        int threads = 256;
        long long total = (long long)n * 4;
        int blocks = (int)((total + threads - 1) / threads);
        dve_scatter_kernel<<<blocks, threads>>>(in, idx, (float4*)out, n);
    }
    {
        int threads = 256;
        int total4 = m * 4;                           // 2,000,000 float4s
        int nthreads = (total4 + 2) / 3;              // ~666,667
        int blocks = (nthreads + threads - 1) / threads;  // 2605
        dve_finalize_kernel<<<blocks, threads>>>((float4*)out, total4);
    }
}

// round 17
// speedup vs baseline: 1.0915x; 1.0276x over previous
#include <cuda_runtime.h>
#include <cuda_bf16.h>

// scatter_mean: out[m, c] = sum_{i: idx[i]==m} in[i, c] / max(count_m, 1)
// N = 4,000,000 rows, C = 16 channels fp32, M = 500,000 segments, idx int32.
//
// Structure (R11-validated): HW memsets -> quad-REDG scatter -> MLP=3
// finalize. This round: scatter gets 2 grid-strided items per thread with
// all loads hoisted (MLP=4/thread) to close the L1=73.4% -> ~100% gap
// (R12 profile: DRAM-latency exposure starves the L1tex atomic stream).

#define CHANNELS 16
#define MAX_SEGMENTS 500000

__device__ float g_counts[MAX_SEGMENTS];

// ---------------------------------------------------------------------------
// Scatter-add, quad-per-row, 2 lane-items per thread (grid-strided).
// Item = (row, q): lane q of row's 64B destination. All 4 loads (2 idx +
// 2 float4) are issued before any RED so DRAM latency overlaps the atomic
// stream. Every LDG is warp-contiguous; lane 0 of each quad adds the count.
// ---------------------------------------------------------------------------
__global__ void __launch_bounds__(256, 8)
dve_scatter_kernel(const float4* __restrict__ in,
                   const int* __restrict__ idx,
                   float4* __restrict__ sums4,
                   long long total)            // total = 4*n lane-items
{
    long long stride = (long long)gridDim.x * blockDim.x;
    long long t0 = (long long)blockIdx.x * blockDim.x + threadIdx.x;
    long long t1 = t0 + stride;

    if (t1 < total) {
        int row0 = (int)(t0 >> 2), q0 = (int)(t0 & 3);
        int row1 = (int)(t1 >> 2), q1 = (int)(t1 & 3);

        // Batch all loads (independent) for MLP.
        int s0 = __ldg(idx + row0);
        int s1 = __ldg(idx + row1);
        float4 v0 = __ldg(in + (size_t)row0 * 4 + q0);
        float4 v1 = __ldg(in + (size_t)row1 * 4 + q1);

        float4* p0 = sums4 + (size_t)s0 * 4 + q0;
        float4* p1 = sums4 + (size_t)s1 * 4 + q1;
        asm volatile("red.global.add.v4.f32 [%0], {%1, %2, %3, %4};"
                     :: "l"(p0), "f"(v0.x), "f"(v0.y), "f"(v0.z), "f"(v0.w)
                     : "memory");
        asm volatile("red.global.add.v4.f32 [%0], {%1, %2, %3, %4};"
                     :: "l"(p1), "f"(v1.x), "f"(v1.y), "f"(v1.z), "f"(v1.w)
                     : "memory");

        if (q0 == 0) atomicAdd(&g_counts[s0], 1.0f);
        if (q1 == 0) atomicAdd(&g_counts[s1], 1.0f);
    } else if (t0 < total) {
        int row = (int)(t0 >> 2), q = (int)(t0 & 3);
        int s = __ldg(idx + row);
        float4 v = __ldg(in + (size_t)row * 4 + q);
        float4* p = sums4 + (size_t)s * 4 + q;
        asm volatile("red.global.add.v4.f32 [%0], {%1, %2, %3, %4};"
                     :: "l"(p), "f"(v.x), "f"(v.y), "f"(v.z), "f"(v.w)
                     : "memory");
        if (q == 0) atomicAdd(&g_counts[s], 1.0f);
    }
}

// ---------------------------------------------------------------------------
// Finalize: 3 grid-strided float4s per thread, all loads issued before any
// dependent math. Every LDG/STG is warp-contiguous. (R11 form, plateau.)
// ---------------------------------------------------------------------------
__global__ void __launch_bounds__(256, 8)
dve_finalize_kernel(float4* __restrict__ out, int total4) {
    int stride = gridDim.x * blockDim.x;
    int t0 = blockIdx.x * blockDim.x + threadIdx.x;
    int t1 = t0 + stride;
    int t2 = t1 + stride;

    if (t2 < total4) {
        float c0 = g_counts[t0 >> 2];
        float c1 = g_counts[t1 >> 2];
        float c2 = g_counts[t2 >> 2];
        float4 v0 = out[t0];
        float4 v1 = out[t1];
        float4 v2 = out[t2];
        float i0 = 1.0f / fmaxf(c0, 1.0f);
        float i1 = 1.0f / fmaxf(c1, 1.0f);
        float i2 = 1.0f / fmaxf(c2, 1.0f);
        v0.x *= i0; v0.y *= i0; v0.z *= i0; v0.w *= i0;
        v1.x *= i1; v1.y *= i1; v1.z *= i1; v1.w *= i1;
        v2.x *= i2; v2.y *= i2; v2.z *= i2; v2.w *= i2;
        out[t0] = v0;
        out[t1] = v1;
        out[t2] = v2;
    } else {
        for (int t = t0; t < total4; t += stride) {
            float inv = 1.0f / fmaxf(g_counts[t >> 2], 1.0f);
            float4 v = out[t];
            v.x *= inv; v.y *= inv; v.z *= inv; v.w *= inv;
            out[t] = v;
        }
    }
}

// ---------------------------------------------------------------------------
// Launch
// ---------------------------------------------------------------------------
extern "C" void kernel_launch(void* const* d_in, const int* in_sizes, int n_in,
                              void* d_out, int out_size) {
    const float4* in = (const float4*)d_in[0];   // [N, 16] fp32
    const int* idx = (const int*)d_in[1];        // [N] int32
    float* out = (float*)d_out;                  // [M, 16] fp32

    int n = in_sizes[0] / CHANNELS;   // 4,000,000
    int m = out_size / CHANNELS;      // 500,000

    // Zero sums + counts via HW memset nodes (graph-capturable, no alloc).
    void* counts_ptr = nullptr;
    cudaGetSymbolAddress(&counts_ptr, g_counts);
    cudaMemsetAsync(d_out, 0, (size_t)out_size * sizeof(float), 0);
    cudaMemsetAsync(counts_ptr, 0, (size_t)m * sizeof(float), 0);

    {
        int threads = 256;
        long long total = (long long)n * 4;       // 16M lane-items
        long long nthreads = (total + 1) / 2;     // 8M threads
        int blocks = (int)((nthreads + threads - 1) / threads);  // 31250
        dve_scatter_kernel<<<blocks, threads>>>(in, idx, (float4*)out, total);
    }
    {
        int threads = 256;
        int total4 = m * 4;                           // 2,000,000 float4s
        int nthreads = (total4 + 2) / 3;              // ~666,667
        int blocks = (nthreads + threads - 1) / threads;  // 2605
        dve_finalize_kernel<<<blocks, threads>>>((float4*)out, total4);
    }
}